// round 16
// baseline (speedup 1.0000x reference)
#include <cuda_runtime.h>

#define NMAX 20000
#define EMAX 200000
#define C_   14
#define F_   128
#define TIL  64

typedef unsigned int u32;

// ---- scratch ----
__device__ __align__(16) u32 g_wt[82944];   // bf16 fragment-major weights (uint2 entries)
__device__ __align__(16) u32 g_hbf[(size_t)NMAX * 64];  // h in bf16 (64 u32 per node)
__device__ __align__(16) float g_ef_sum[(size_t)NMAX * F_];
__device__ float g_x_acc [(size_t)NMAX * C_ * 3];
__device__ float g_cnt_row[NMAX];
__device__ float g_cnt_col[NMAX];
__device__ float g_pooled [NMAX * 3];
__device__ int   g_csum   [NMAX];

// weight image offsets in uint2 units
#define WB_E1 0
#define WB_E2 12288
#define WB_C1 16384
#define WB_C2 20480
#define WB_RW 20992
#define WB_N1 29184
#define WB_N2 37376

__device__ __forceinline__ float sigm_(float v) { return 1.f / (1.f + __expf(-v)); }
__device__ __forceinline__ float silu_(float v) { return v * sigm_(v); }
__device__ __forceinline__ u32 packbf(float lo, float hi) {
    u32 r; asm("cvt.rn.bf16x2.f32 %0, %1, %2;" : "=r"(r) : "f"(hi), "f"(lo)); return r;
}
__device__ __forceinline__ void red2(float* addr, float a, float b) {
    asm volatile("red.global.add.v2.f32 [%0], {%1, %2};"
                 :: "l"(addr), "f"(a), "f"(b) : "memory");
}

__device__ __forceinline__ void mma16(float4& d, u32 a0, u32 a1, u32 a2, u32 a3,
                                      u32 b0, u32 b1) {
    asm volatile(
        "mma.sync.aligned.m16n8k16.row.col.f32.bf16.bf16.f32 "
        "{%0,%1,%2,%3},{%4,%5,%6,%7},{%8,%9},{%0,%1,%2,%3};"
        : "+f"(d.x), "+f"(d.y), "+f"(d.z), "+f"(d.w)
        : "r"(a0), "r"(a1), "r"(a2), "r"(a3), "r"(b0), "r"(b1));
}

// A: row-major bf16 buffer, stride S in u32 units. MT m16 tiles, NT n8 tiles.
template<int S, int MT, int NT>
__device__ __forceinline__ void gemm_bf(const u32* as, const uint2* wf,
                                        int nt0, int ks0, int nks, int KST,
                                        int lane, float4 d[MT][NT])
{
    u32 base_sa = (u32)__cvta_generic_to_shared(as);
    u32 off0 = ((u32)(lane & 15) * S + (u32)(lane >> 4) * 4) * 4;
    #pragma unroll
    for (int ks = 0; ks < nks; ++ks) {
        u32 a[MT][4];
        #pragma unroll
        for (int mt = 0; mt < MT; ++mt) {
            u32 sa = base_sa + off0 + (u32)(mt * 16 * S + ks * 8) * 4;
            asm volatile("ldmatrix.sync.aligned.m8n8.x4.shared.b16 {%0,%1,%2,%3}, [%4];"
                         : "=r"(a[mt][0]), "=r"(a[mt][1]), "=r"(a[mt][2]), "=r"(a[mt][3])
                         : "r"(sa));
        }
        #pragma unroll
        for (int nt = 0; nt < NT; ++nt) {
            uint2 b = wf[((size_t)(nt0 + nt) * KST + ks0 + ks) * 32 + lane];
            #pragma unroll
            for (int mt = 0; mt < MT; ++mt)
                mma16(d[mt][nt], a[mt][0], a[mt][1], a[mt][2], a[mt][3], b.x, b.y);
        }
    }
}

__device__ __forceinline__ void store_bf(u32* buf, int S, int g, int f, int mt,
                                         float4 v) {
    buf[(mt * 16 + g) * S + (f >> 1)]     = packbf(v.x, v.y);
    buf[(mt * 16 + g + 8) * S + (f >> 1)] = packbf(v.z, v.w);
}

// ---------------------------------------------------------------------------
__global__ void k_zero(int n_nodes) {
    int t0 = n_nodes * F_, t1 = t0 + n_nodes * C_ * 3, t2 = t1 + n_nodes, t3 = t2 + n_nodes;
    for (int i = blockIdx.x * blockDim.x + threadIdx.x; i < t3; i += gridDim.x * blockDim.x) {
        if (i < t0)       g_ef_sum[i] = 0.f;
        else if (i < t1)  g_x_acc[i - t0] = 0.f;
        else if (i < t2)  g_cnt_row[i - t1] = 0.f;
        else              g_cnt_col[i - t2] = 0.f;
    }
}

__global__ void k_prep(const float* __restrict__ x, const float* __restrict__ cw, int N) {
    int n = blockIdx.x * blockDim.x + threadIdx.x;
    if (n >= N) return;
    int s = 0; float px = 0.f, py = 0.f, pz = 0.f;
    #pragma unroll
    for (int i = 0; i < C_; ++i) {
        float w = cw[n * C_ + i];
        if (w != 0.f) {
            s++; px += x[n * 42 + i * 3]; py += x[n * 42 + i * 3 + 1]; pz += x[n * 42 + i * 3 + 2];
        }
    }
    g_csum[n] = s;
    float inv = 1.f / (float)(s > 0 ? s : 1);
    g_pooled[n * 3] = px * inv; g_pooled[n * 3 + 1] = py * inv; g_pooled[n * 3 + 2] = pz * inv;
}

__global__ void k_hprep(const float* __restrict__ h, int N) {
    int i = blockIdx.x * blockDim.x + threadIdx.x;
    if (i < N * 32) {
        float4 v = *(const float4*)(h + (size_t)i * 4);
        ((uint2*)g_hbf)[i] = make_uint2(packbf(v.x, v.y), packbf(v.z, v.w));
    }
}

__global__ void k_wprep(const float* __restrict__ e_w1, const float* __restrict__ e_w2,
                        const float* __restrict__ c_w1, const float* __restrict__ c_w2,
                        const float* __restrict__ rad_w, const float* __restrict__ n_w1,
                        const float* __restrict__ n_w2) {
    int t = blockIdx.x * blockDim.x + threadIdx.x;
    if (t >= 41472) return;
    int u = t, base; const float* W; int KST, Ncol;
    if      (u < 12288) { base = WB_E1; W = e_w1; KST = 24; Ncol = 128; }
    else if (u < 16384) { u -= 12288; base = WB_E2; W = e_w2;  KST = 8;  Ncol = 128; }
    else if (u < 20480) { u -= 16384; base = WB_C1; W = c_w1;  KST = 8;  Ncol = 128; }
    else if (u < 20992) { u -= 20480; base = WB_C2; W = c_w2;  KST = 8;  Ncol = 14;  }
    else if (u < 29184) { u -= 20992; base = WB_RW; W = rad_w; KST = 16; Ncol = 128; }
    else if (u < 37376) { u -= 29184; base = WB_N1; W = n_w1;  KST = 16; Ncol = 128; }
    else                { u -= 37376; base = WB_N2; W = n_w2;  KST = 8;  Ncol = 128; }
    int lane = u & 31, ks = (u >> 5) % KST, nt = u / (KST * 32);
    int g = lane >> 2, tig = lane & 3;
    int n = nt * 8 + g, k = ks * 16 + 2 * tig;
    uint2 e = make_uint2(0u, 0u);
    if (n < Ncol) {
        e.x = packbf(W[k * Ncol + n],       W[(k + 1) * Ncol + n]);
        e.y = packbf(W[(k + 8) * Ncol + n], W[(k + 9) * Ncol + n]);
    }
    ((uint2*)g_wt)[base + u] = e;
}

// ---------------------------------------------------------------------------
// K_FUSED — 64-edge tiles, 512 threads / 16 warps, NT=1 x MT=4 per warp
// smem (u32 units, total 22272 = 89088 B):
//  [0..8448)      in_s [64][132] (ph1-2) | later bufA[64][68]@0,
//                 cm_s(f32)@4352(1024), gp@5376(1152), gate@6528(64)
//  [8448..22016)  wscF (f32) 16x848 (ph1) | later bufR@8448(4352), bufT@12800(4352)
//  [22016..22272) s_row 64 | s_col 64 | s_cs 64 | inv_norm 64
// ---------------------------------------------------------------------------
#define SMEM_F (22272 * 4)

__global__ __launch_bounds__(512, 2) void k_fused(
    const float* __restrict__ x, const float* __restrict__ attr,
    const float* __restrict__ cw, const int* __restrict__ row,
    const int* __restrict__ col, const float* __restrict__ rad_b,
    const float* __restrict__ e_b1, const float* __restrict__ e_b2,
    const float* __restrict__ att_w, const float* __restrict__ att_b,
    const float* __restrict__ c_b1, const float* __restrict__ c_b2, int E)
{
    extern __shared__ u32 smu[];
    u32*   in_s   = smu;
    u32*   bufA   = smu;
    float* cm_s   = (float*)(smu + 4352);
    float* gp     = (float*)(smu + 5376);
    float* gate_s = (float*)(smu + 6528);
    float* wscF   = (float*)(smu + 8448);
    u32*   bufR   = smu + 8448;
    u32*   bufT   = smu + 12800;
    int*   s_row  = (int*)(smu + 22016);
    int*   s_col  = s_row + 64;
    int*   s_cs   = s_col + 64;
    float* inv_norm = (float*)(s_cs + 64);

    int tid = threadIdx.x, lane = tid & 31, w = tid >> 5;
    int g = lane >> 2, tig = lane & 3;
    int e0 = blockIdx.x * TIL;
    const uint2* gw = (const uint2*)g_wt;

    if (tid < TIL) {
        int e = e0 + tid; if (e >= E) e = E - 1;
        int r = row[e];
        s_row[tid] = r; s_col[tid] = col[e]; s_cs[tid] = g_csum[r];
    }
    __syncthreads();

    // ======== phase 1: radial einsum prologue (16 warps x 4 edges, bf16 mma) ====
    {
        float* W = wscF + w * 848;
        float *s_T = W, *s_xr = W + 272, *s_xc = W + 320,
              *s_cwr = W + 368, *s_cwc = W + 384, *s_ar = W + 400, *s_ac = W + 624;

        float p_ar[7], p_ac[7];
        int p_r, p_c;
        {
            int e = e0 + w * 4; if (e >= E) e = E - 1;
            p_r = row[e]; p_c = col[e];
            #pragma unroll
            for (int q = 0; q < 7; ++q) {
                p_ar[q] = attr[p_r * 224 + q * 32 + lane];
                p_ac[q] = attr[p_c * 224 + q * 32 + lane];
            }
        }

        for (int it = 0; it < 4; ++it) {
            int m = w * 4 + it;
            int r = p_r, c = p_c;

            #pragma unroll
            for (int q = 0; q < 7; ++q) {
                s_ar[q * 32 + lane] = p_ar[q];
                s_ac[q * 32 + lane] = p_ac[q];
            }
            s_xr[lane] = x[r * 42 + lane];
            s_xc[lane] = x[c * 42 + lane];
            if (lane < 16) {
                s_xr[32 + lane] = (lane < 10) ? x[r * 42 + 32 + lane] : 0.f;
                s_xc[32 + lane] = (lane < 10) ? x[c * 42 + 32 + lane] : 0.f;
                s_cwr[lane] = (lane < 14) ? cw[r * C_ + lane] : 0.f;
                s_cwc[lane] = (lane < 14) ? cw[c * C_ + lane] : 0.f;
            }
            if (it < 3) {
                int e = e0 + m + 1; if (e >= E) e = E - 1;
                p_r = row[e]; p_c = col[e];
                #pragma unroll
                for (int q = 0; q < 7; ++q) {
                    p_ar[q] = attr[p_r * 224 + q * 32 + lane];
                    p_ac[q] = attr[p_c * 224 + q * 32 + lane];
                }
            }
            __syncwarp();

            float msgv[2][4];
            {
                float xr0[3] = { s_xr[g * 3], s_xr[g * 3 + 1], s_xr[g * 3 + 2] };
                float xr1[3] = { s_xr[(g + 8) * 3], s_xr[(g + 8) * 3 + 1], s_xr[(g + 8) * 3 + 2] };
                float cw0 = s_cwr[g], cw1 = s_cwr[g + 8];
                #pragma unroll
                for (int jj = 0; jj < 4; ++jj) {
                    int cj = 2 * tig + (jj & 1) + (jj >> 1) * 8;
                    float xc0 = s_xc[cj * 3], xc1 = s_xc[cj * 3 + 1], xc2 = s_xc[cj * 3 + 2];
                    float cwc = s_cwc[cj];
                    float d0x = xr0[0] - xc0, d0y = xr0[1] - xc1, d0z = xr0[2] - xc2;
                    float d1x = xr1[0] - xc0, d1y = xr1[1] - xc1, d1z = xr1[2] - xc2;
                    msgv[0][jj] = sqrtf(d0x*d0x + d0y*d0y + d0z*d0z) * cw0 * cwc;
                    msgv[1][jj] = sqrtf(d1x*d1x + d1y*d1y + d1z*d1z) * cw1 * cwc;
                }
            }

            float4 dT[2] = {make_float4(0,0,0,0), make_float4(0,0,0,0)};
            {
                u32 a0 = packbf(msgv[0][0], msgv[0][1]);
                u32 a1 = packbf(msgv[1][0], msgv[1][1]);
                u32 a2 = packbf(msgv[0][2], msgv[0][3]);
                u32 a3 = packbf(msgv[1][2], msgv[1][3]);
                int kb0 = 2 * tig, kb1 = 2 * tig + 8;
                #pragma unroll
                for (int nt = 0; nt < 2; ++nt) {
                    int n = nt * 8 + g;
                    u32 b0 = packbf(s_ac[kb0 * 16 + n], s_ac[(kb0 + 1) * 16 + n]);
                    u32 b1 = (kb1 < 14)
                        ? packbf(s_ac[kb1 * 16 + n],
                                 (kb1 + 1 < 14) ? s_ac[(kb1 + 1) * 16 + n] : 0.f)
                        : 0u;
                    mma16(dT[nt], a0, a1, a2, a3, b0, b1);
                }
            }
            #pragma unroll
            for (int nt = 0; nt < 2; ++nt) {
                int fc = nt * 8 + 2 * tig;
                s_T[g * 17 + fc]           = dT[nt].x;
                s_T[g * 17 + fc + 1]       = dT[nt].y;
                s_T[(g + 8) * 17 + fc]     = dT[nt].z;
                s_T[(g + 8) * 17 + fc + 1] = dT[nt].w;
            }
            __syncwarp();

            float4 dR[2] = {make_float4(0,0,0,0), make_float4(0,0,0,0)};
            {
                int kb0 = 2 * tig, kb1 = 2 * tig + 8;
                u32 a0 = packbf(s_ar[kb0 * 16 + g],     s_ar[(kb0 + 1) * 16 + g]);
                u32 a1 = packbf(s_ar[kb0 * 16 + g + 8], s_ar[(kb0 + 1) * 16 + g + 8]);
                u32 a2 = 0u, a3 = 0u;
                if (kb1 < 14) {
                    float v2 = (kb1 + 1 < 14) ? s_ar[(kb1 + 1) * 16 + g] : 0.f;
                    float v3 = (kb1 + 1 < 14) ? s_ar[(kb1 + 1) * 16 + g + 8] : 0.f;
                    a2 = packbf(s_ar[kb1 * 16 + g], v2);
                    a3 = packbf(s_ar[kb1 * 16 + g + 8], v3);
                }
                #pragma unroll
                for (int nt = 0; nt < 2; ++nt) {
                    int n = nt * 8 + g;
                    u32 b0 = packbf(s_T[kb0 * 17 + n], s_T[(kb0 + 1) * 17 + n]);
                    u32 b1 = packbf(s_T[kb1 * 17 + n], s_T[(kb1 + 1) * 17 + n]);
                    mma16(dR[nt], a0, a1, a2, a3, b0, b1);
                }
            }

            float ss = dR[0].x*dR[0].x + dR[0].y*dR[0].y + dR[0].z*dR[0].z + dR[0].w*dR[0].w
                     + dR[1].x*dR[1].x + dR[1].y*dR[1].y + dR[1].z*dR[1].z + dR[1].w*dR[1].w;
            #pragma unroll
            for (int o = 16; o; o >>= 1) ss += __shfl_xor_sync(0xffffffffu, ss, o);
            if (lane == 0) inv_norm[m] = 1.f / (sqrtf(ss) + 1.f);

            #pragma unroll
            for (int nt = 0; nt < 2; ++nt) {
                int fc = nt * 8 + 2 * tig;
                in_s[m * 132 + ((g * 16 + fc) >> 1)]       = packbf(dR[nt].x, dR[nt].y);
                in_s[m * 132 + (((g + 8) * 16 + fc) >> 1)] = packbf(dR[nt].z, dR[nt].w);
            }
            __syncwarp();
        }
    }
    __syncthreads();

    // ======== phase 2: radial GEMM K=256 ========
    float4 d[4][1];
    #pragma unroll
    for (int mt = 0; mt < 4; ++mt) d[mt][0] = make_float4(0.f, 0.f, 0.f, 0.f);
    gemm_bf<132, 4, 1>(in_s, gw + WB_RW, w, 0, 16, 16, lane, d);

    // epilogue -> bufR (aliases dead wscF)
    {
        int f = w * 8 + 2 * tig;
        float2 rb = *(const float2*)(rad_b + f);
        #pragma unroll
        for (int mt = 0; mt < 4; ++mt) {
            int e = mt * 16 + g;
            float na = inv_norm[e], nb = inv_norm[e + 8];
            bufR[(mt * 16 + g) * 68 + (f >> 1)] =
                packbf((d[mt][0].x + rb.x) * na, (d[mt][0].y + rb.y) * na);
            bufR[(mt * 16 + g + 8) * 68 + (f >> 1)] =
                packbf((d[mt][0].z + rb.x) * nb, (d[mt][0].w + rb.y) * nb);
        }
    }
    __syncthreads();

    // stage h[row] -> bufA
    for (int i = tid; i < 2048; i += 512) {
        int e = i >> 5, q = i & 31;
        *(uint2*)(bufA + e * 68 + q * 2) =
            *(const uint2*)(g_hbf + (size_t)s_row[e] * 64 + q * 2);
    }
    __syncthreads();

    // ======== GEMM1 (K=384) ========
    #pragma unroll
    for (int mt = 0; mt < 4; ++mt) d[mt][0] = make_float4(0.f, 0.f, 0.f, 0.f);
    gemm_bf<68, 4, 1>(bufA, gw + WB_E1, w, 0, 8, 24, lane, d);
    __syncthreads();
    for (int i = tid; i < 2048; i += 512) {       // stage h[col]
        int e = i >> 5, q = i & 31;
        *(uint2*)(bufA + e * 68 + q * 2) =
            *(const uint2*)(g_hbf + (size_t)s_col[e] * 64 + q * 2);
    }
    __syncthreads();
    gemm_bf<68, 4, 1>(bufA, gw + WB_E1, w, 8, 8, 24, lane, d);
    gemm_bf<68, 4, 1>(bufR, gw + WB_E1, w, 16, 8, 24, lane, d);

    // ep1: t1 = silu(D + e_b1) -> bufT
    {
        int f = w * 8 + 2 * tig;
        float2 bb = *(const float2*)(e_b1 + f);
        #pragma unroll
        for (int mt = 0; mt < 4; ++mt)
            store_bf(bufT, 68, g, f, mt,
                make_float4(silu_(d[mt][0].x + bb.x), silu_(d[mt][0].y + bb.y),
                            silu_(d[mt][0].z + bb.x), silu_(d[mt][0].w + bb.y)));
    }
    __syncthreads();

    // ======== GEMM2: e_w2 ========
    #pragma unroll
    for (int mt = 0; mt < 4; ++mt) d[mt][0] = make_float4(0.f, 0.f, 0.f, 0.f);
    gemm_bf<68, 4, 1>(bufT, gw + WB_E2, w, 0, 8, 8, lane, d);

    // ep2: t2 = silu(+e_b2); gate; ef -> bufR + vector reds
    {
        int f = w * 8 + 2 * tig;
        float2 bb = *(const float2*)(e_b2 + f);
        float2 aw = *(const float2*)(att_w + f);
        float p[8];
        #pragma unroll
        for (int mt = 0; mt < 4; ++mt) {
            float c0 = silu_(d[mt][0].x + bb.x), c1 = silu_(d[mt][0].y + bb.y);
            float c2 = silu_(d[mt][0].z + bb.x), c3 = silu_(d[mt][0].w + bb.y);
            d[mt][0] = make_float4(c0, c1, c2, c3);
            p[mt * 2 + 0] = c0 * aw.x + c1 * aw.y;
            p[mt * 2 + 1] = c2 * aw.x + c3 * aw.y;
        }
        #pragma unroll
        for (int o = 1; o <= 2; o <<= 1)
            #pragma unroll
            for (int q = 0; q < 8; ++q) p[q] += __shfl_xor_sync(0xffffffffu, p[q], o);
        if (tig == 0) {
            #pragma unroll
            for (int q = 0; q < 8; ++q) {
                int e = (q >> 1) * 16 + g + (q & 1) * 8;
                gp[w * 72 + e] = p[q];
            }
        }
    }
    __syncthreads();
    if (tid < TIL) {
        float s = __ldg(att_b);
        #pragma unroll
        for (int j = 0; j < 16; ++j) s += gp[j * 72 + tid];
        gate_s[tid] = sigm_(s);
    }
    __syncthreads();
    {
        int f = w * 8 + 2 * tig;
        #pragma unroll
        for (int mt = 0; mt < 4; ++mt) {
            int ea = mt * 16 + g, eb = ea + 8;
            float ga = gate_s[ea], gb = gate_s[eb];
            float c0 = d[mt][0].x * ga, c1 = d[mt][0].y * ga;
            float c2 = d[mt][0].z * gb, c3 = d[mt][0].w * gb;
            store_bf(bufR, 68, g, f, mt, make_float4(c0, c1, c2, c3));
            if (e0 + ea < E)
                red2(g_ef_sum + (size_t)s_col[ea] * F_ + f, c0, c1);
            if (e0 + eb < E)
                red2(g_ef_sum + (size_t)s_col[eb] * F_ + f, c2, c3);
        }
    }
    if (tid < TIL && e0 + tid < E) {
        atomicAdd(&g_cnt_col[s_col[tid]], 1.f);
        atomicAdd(&g_cnt_row[s_row[tid]], 1.f);
    }
    __syncthreads();

    // ======== GEMM3: c_w1 ========
    #pragma unroll
    for (int mt = 0; mt < 4; ++mt) d[mt][0] = make_float4(0.f, 0.f, 0.f, 0.f);
    gemm_bf<68, 4, 1>(bufR, gw + WB_C1, w, 0, 8, 8, lane, d);
    {
        int f = w * 8 + 2 * tig;
        float2 bb = *(const float2*)(c_b1 + f);
        #pragma unroll
        for (int mt = 0; mt < 4; ++mt)
            store_bf(bufT, 68, g, f, mt,
                make_float4(silu_(d[mt][0].x + bb.x), silu_(d[mt][0].y + bb.y),
                            silu_(d[mt][0].z + bb.x), silu_(d[mt][0].w + bb.y)));
    }
    __syncthreads();

    // ======== GEMM4: c_w2 (N=16, warps 0-1) ========
    if (w < 2) {
        float4 dc[4];
        #pragma unroll
        for (int mt = 0; mt < 4; ++mt) dc[mt] = make_float4(0.f, 0.f, 0.f, 0.f);
        #pragma unroll
        for (int ks = 0; ks < 8; ++ks) {
            uint2 b = gw[WB_C2 + ((size_t)w * 8 + ks) * 32 + lane];
            #pragma unroll
            for (int mt = 0; mt < 4; ++mt) {
                const u32* r0 = bufT + (mt * 16 + g) * 68 + ks * 8;
                const u32* r1 = bufT + (mt * 16 + g + 8) * 68 + ks * 8;
                mma16(dc[mt], r0[tig], r1[tig], r0[tig + 4], r1[tig + 4], b.x, b.y);
            }
        }
        int o = w * 8 + 2 * tig;
        float cbx = (o < 14)     ? __ldg(c_b2 + o)     : 0.f;
        float cby = (o + 1 < 14) ? __ldg(c_b2 + o + 1) : 0.f;
        #pragma unroll
        for (int mt = 0; mt < 4; ++mt) {
            *(float2*)(cm_s + (mt * 16 + g) * 16 + o) =
                make_float2(dc[mt].x + cbx, dc[mt].y + cby);
            *(float2*)(cm_s + (mt * 16 + g + 8) * 16 + o) =
                make_float2(dc[mt].z + cbx, dc[mt].w + cby);
        }
    }
    __syncthreads();

    // ======== roller pooling + x scatter ========
    for (int idx = tid; idx < TIL * 42; idx += 512) {
        int m = idx / 42, rem = idx - m * 42;
        int e = e0 + m;
        if (e < E) {
            int i = rem / 3, dd = rem - i * 3;
            int ws = 15 - s_cs[m];
            if (ws < 1)  ws = 1;
            if (ws > 14) ws = 14;
            int end = i + ws; if (end > 14) end = 14;
            float ps = 0.f;
            for (int q = i; q < end; ++q) ps += cm_s[m * 16 + q];
            float pooled = ps / (float)ws;
            float cd = x[(size_t)s_row[m] * 42 + rem] - g_pooled[s_col[m] * 3 + dd];
            atomicAdd(&g_x_acc[(size_t)s_row[m] * 42 + rem], cd * pooled);
        }
    }
}

// ---------------------------------------------------------------------------
// K_NODE (unchanged structure; gemm calls re-templated)
// ---------------------------------------------------------------------------
#define SMEM_N (7008 * 4)
__global__ __launch_bounds__(128) void k_node(
    const float* __restrict__ h, const float* __restrict__ x,
    const float* __restrict__ n_b1, const float* __restrict__ n_b2,
    const float* __restrict__ ln_g, const float* __restrict__ ln_b,
    float* __restrict__ out, int N)
{
    extern __shared__ u32 smu[];
    u32*   in_s = smu;
    u32*   bufT = smu + 4224;
    float* gp1  = (float*)(smu + 6400);
    float* gp2  = gp1 + 144;
    float* mu_s = gp2 + 144;
    float* rs_s = mu_s + 32;
    float* ic_s = rs_s + 32;

    int tid = threadIdx.x, lane = tid & 31, w = tid >> 5;
    int g = lane >> 2, tig = lane & 3, nt0 = w * 4;
    int n0 = blockIdx.x * 32;
    const uint2* gw = (const uint2*)g_wt;

    if (tid < 32) {
        int n = n0 + tid;
        float c = (n < N) ? g_cnt_col[n] : 1.f;
        ic_s[tid] = 1.f / fmaxf(c, 1.f);
    }
    __syncthreads();

    for (int i = tid; i < 2048; i += 128) {
        int e = i >> 6, q = i & 63;
        int n = n0 + e; if (n >= N) n = N - 1;
        if (q < 32) {
            *(uint2*)(in_s + e * 132 + q * 2) =
                *(const uint2*)(g_hbf + (size_t)n * 64 + q * 2);
        } else {
            float4 v = *(const float4*)(g_ef_sum + (size_t)n * F_ + (q - 32) * 4);
            float ic = ic_s[e];
            *(uint2*)(in_s + e * 132 + q * 2) =
                make_uint2(packbf(v.x * ic, v.y * ic), packbf(v.z * ic, v.w * ic));
        }
    }
    __syncthreads();

    float4 d[2][4];
    #pragma unroll
    for (int mt = 0; mt < 2; ++mt)
        #pragma unroll
        for (int nt = 0; nt < 4; ++nt) d[mt][nt] = make_float4(0.f, 0.f, 0.f, 0.f);
    gemm_bf<132, 2, 4>(in_s, gw + WB_N1, nt0, 0, 16, 16, lane, d);
    #pragma unroll
    for (int mt = 0; mt < 2; ++mt)
        #pragma unroll
        for (int nt = 0; nt < 4; ++nt) {
            int f = w * 32 + nt * 8 + 2 * tig;
            float2 bb = *(const float2*)(n_b1 + f);
            store_bf(bufT, 68, g, f, mt,
                make_float4(silu_(d[mt][nt].x + bb.x), silu_(d[mt][nt].y + bb.y),
                            silu_(d[mt][nt].z + bb.x), silu_(d[mt][nt].w + bb.y)));
        }
    __syncthreads();

    #pragma unroll
    for (int mt = 0; mt < 2; ++mt)
        #pragma unroll
        for (int nt = 0; nt < 4; ++nt) d[mt][nt] = make_float4(0.f, 0.f, 0.f, 0.f);
    gemm_bf<68, 2, 4>(bufT, gw + WB_N2, nt0, 0, 8, 8, lane, d);

    {
        float p1[4] = {0,0,0,0}, p2[4] = {0,0,0,0};
        #pragma unroll
        for (int mt = 0; mt < 2; ++mt) {
            int na = n0 + mt * 16 + g, nb = na + 8;
            if (na >= N) na = N - 1;
            if (nb >= N) nb = N - 1;
            #pragma unroll
            for (int nt = 0; nt < 4; ++nt) {
                int f = w * 32 + nt * 8 + 2 * tig;
                float2 bb = *(const float2*)(n_b2 + f);
                float2 ra = *(const float2*)(h + (size_t)na * F_ + f);
                float2 rb = *(const float2*)(h + (size_t)nb * F_ + f);
                float h0 = ra.x + d[mt][nt].x + bb.x, h1 = ra.y + d[mt][nt].y + bb.y;
                float h2 = rb.x + d[mt][nt].z + bb.x, h3 = rb.y + d[mt][nt].w + bb.y;
                d[mt][nt] = make_float4(h0, h1, h2, h3);
                p1[mt*2]   += h0 + h1;  p2[mt*2]   += h0*h0 + h1*h1;
                p1[mt*2+1] += h2 + h3;  p2[mt*2+1] += h2*h2 + h3*h3;
            }
        }
        #pragma unroll
        for (int o = 1; o <= 2; o <<= 1)
            #pragma unroll
            for (int q = 0; q < 4; ++q) {
                p1[q] += __shfl_xor_sync(0xffffffffu, p1[q], o);
                p2[q] += __shfl_xor_sync(0xffffffffu, p2[q], o);
            }
        if (tig == 0) {
            #pragma unroll
            for (int q = 0; q < 4; ++q) {
                int e = (q >> 1) * 16 + g + (q & 1) * 8;
                gp1[w * 36 + e] = p1[q];
                gp2[w * 36 + e] = p2[q];
            }
        }
    }
    __syncthreads();
    if (tid < 32) {
        float s1 = gp1[tid] + gp1[36 + tid] + gp1[72 + tid] + gp1[108 + tid];
        float s2 = gp2[tid] + gp2[36 + tid] + gp2[72 + tid] + gp2[108 + tid];
        float mu = s1 * (1.f / 128.f);
        float var = fmaxf(s2 * (1.f / 128.f) - mu * mu, 0.f);
        mu_s[tid] = mu;
        rs_s[tid] = rsqrtf(var + 1e-5f);
    }
    __syncthreads();

    #pragma unroll
    for (int mt = 0; mt < 2; ++mt) {
        int ea = mt * 16 + g, eb = ea + 8;
        int na = n0 + ea, nb = n0 + eb;
        float mua = mu_s[ea], rsa = rs_s[ea];
        float mub = mu_s[eb], rsb = rs_s[eb];
        #pragma unroll
        for (int nt = 0; nt < 4; ++nt) {
            int f = w * 32 + nt * 8 + 2 * tig;
            float2 gv = *(const float2*)(ln_g + f);
            float2 bv = *(const float2*)(ln_b + f);
            if (na < N)
                *(float2*)(out + (size_t)na * F_ + f) = make_float2(
                    (d[mt][nt].x - mua) * rsa * gv.x + bv.x,
                    (d[mt][nt].y - mua) * rsa * gv.y + bv.y);
            if (nb < N)
                *(float2*)(out + (size_t)nb * F_ + f) = make_float2(
                    (d[mt][nt].z - mub) * rsb * gv.x + bv.x,
                    (d[mt][nt].w - mub) * rsb * gv.y + bv.y);
        }
    }

    float* out_x = out + (size_t)N * F_;
    for (int idx = tid; idx < 32 * 42; idx += 128) {
        int m = idx / 42, rem = idx - m * 42;
        int n = n0 + m;
        if (n < N)
            out_x[(size_t)n * 42 + rem] = x[(size_t)n * 42 + rem] +
                g_x_acc[(size_t)n * 42 + rem] / fmaxf(g_cnt_row[n], 1.f);
    }
}

// ---------------------------------------------------------------------------
extern "C" void kernel_launch(void* const* d_in, const int* in_sizes, int n_in,
                              void* d_out, int out_size) {
    const float* h     = (const float*)d_in[0];
    const float* x     = (const float*)d_in[1];
    const float* attr  = (const float*)d_in[2];
    const float* cw    = (const float*)d_in[3];
    const int*   row   = (const int*)d_in[4];
    const int*   col   = (const int*)d_in[5];
    const float* rad_w = (const float*)d_in[6];
    const float* rad_b = (const float*)d_in[7];
    const float* e_w1  = (const float*)d_in[8];
    const float* e_b1  = (const float*)d_in[9];
    const float* e_w2  = (const float*)d_in[10];
    const float* e_b2  = (const float*)d_in[11];
    const float* att_w = (const float*)d_in[12];
    const float* att_b = (const float*)d_in[13];
    const float* c_w1  = (const float*)d_in[14];
    const float* c_b1  = (const float*)d_in[15];
    const float* c_w2  = (const float*)d_in[16];
    const float* c_b2  = (const float*)d_in[17];
    const float* n_w1  = (const float*)d_in[18];
    const float* n_b1  = (const float*)d_in[19];
    const float* n_w2  = (const float*)d_in[20];
    const float* n_b2  = (const float*)d_in[21];
    const float* ln_g  = (const float*)d_in[22];
    const float* ln_b  = (const float*)d_in[23];

    int N = in_sizes[0] / F_;
    int E = in_sizes[4];

    cudaFuncSetAttribute(k_fused, cudaFuncAttributeMaxDynamicSharedMemorySize, SMEM_F);
    cudaFuncSetAttribute(k_node,  cudaFuncAttributeMaxDynamicSharedMemorySize, SMEM_N);

    k_zero<<<256, 256>>>(N);
    k_prep<<<(N + 255) / 256, 256>>>(x, cw, N);
    k_hprep<<<(N * 32 + 255) / 256, 256>>>(h, N);
    k_wprep<<<162, 256>>>(e_w1, e_w2, c_w1, c_w2, rad_w, n_w1, n_w2);
    k_fused<<<(E + TIL - 1) / TIL, 512, SMEM_F>>>(x, attr, cw, row, col, rad_b,
                                                  e_b1, e_b2, att_w, att_b,
                                                  c_b1, c_b2, E);
    k_node<<<(N + 31) / 32, 128, SMEM_N>>>(h, x, n_b1, n_b2,
                                           ln_g, ln_b, (float*)d_out, N);
}

// round 17
// speedup vs baseline: 1.1429x; 1.1429x over previous
#include <cuda_runtime.h>

#define NMAX 20000
#define EMAX 200000
#define C_   14
#define F_   128
#define TIL  32

typedef unsigned int u32;

// ---- scratch ----
__device__ __align__(16) u32 g_wt[82944];   // bf16 fragment-major weights (uint2 entries)
__device__ __align__(16) u32 g_hbf[(size_t)NMAX * 64];  // h in bf16 (64 u32 per node)
__device__ __align__(16) float g_ef_sum[(size_t)NMAX * F_];
__device__ float g_x_acc [(size_t)NMAX * C_ * 3];
__device__ float g_cnt_row[NMAX];
__device__ float g_cnt_col[NMAX];
__device__ float g_pooled [NMAX * 3];
__device__ int   g_csum   [NMAX];

// weight image offsets in uint2 units
#define WB_E1 0
#define WB_E2 12288
#define WB_C1 16384
#define WB_C2 20480
#define WB_RW 20992
#define WB_N1 29184
#define WB_N2 37376

__device__ __forceinline__ float sigm_(float v) { return 1.f / (1.f + __expf(-v)); }
__device__ __forceinline__ float silu_(float v) { return v * sigm_(v); }
__device__ __forceinline__ u32 packbf(float lo, float hi) {
    u32 r; asm("cvt.rn.bf16x2.f32 %0, %1, %2;" : "=r"(r) : "f"(hi), "f"(lo)); return r;
}
// vectorized no-return atomic add (sm_90+)
__device__ __forceinline__ void red2(float* addr, float a, float b) {
    asm volatile("red.global.add.v2.f32 [%0], {%1, %2};"
                 :: "l"(addr), "f"(a), "f"(b) : "memory");
}

// bf16 m16n8k16 (all GEMMs incl. prologue)
__device__ __forceinline__ void mma16(float4& d, u32 a0, u32 a1, u32 a2, u32 a3,
                                      u32 b0, u32 b1) {
    asm volatile(
        "mma.sync.aligned.m16n8k16.row.col.f32.bf16.bf16.f32 "
        "{%0,%1,%2,%3},{%4,%5,%6,%7},{%8,%9},{%0,%1,%2,%3};"
        : "+f"(d.x), "+f"(d.y), "+f"(d.z), "+f"(d.w)
        : "r"(a0), "r"(a1), "r"(a2), "r"(a3), "r"(b0), "r"(b1));
}

// A: row-major bf16 buffer, stride S in u32 units. A-fragments via ldmatrix.x4.
template<int S, int NT>
__device__ __forceinline__ void gemm_bf(const u32* as, const uint2* wf,
                                        int nt0, int ks0, int nks, int KST,
                                        int g, int tig, int lane, float4 d[2][NT])
{
    u32 base_sa = (u32)__cvta_generic_to_shared(as);
    u32 off0 = ((u32)(lane & 15) * S + (u32)(lane >> 4) * 4) * 4;
    #pragma unroll
    for (int ks = 0; ks < nks; ++ks) {
        u32 a[2][4];
        #pragma unroll
        for (int mt = 0; mt < 2; ++mt) {
            u32 sa = base_sa + off0 + (u32)(mt * 16 * S + ks * 8) * 4;
            asm volatile("ldmatrix.sync.aligned.m8n8.x4.shared.b16 {%0,%1,%2,%3}, [%4];"
                         : "=r"(a[mt][0]), "=r"(a[mt][1]), "=r"(a[mt][2]), "=r"(a[mt][3])
                         : "r"(sa));
        }
        #pragma unroll
        for (int nt = 0; nt < NT; ++nt) {
            uint2 b = wf[((size_t)(nt0 + nt) * KST + ks0 + ks) * 32 + lane];
            mma16(d[0][nt], a[0][0], a[0][1], a[0][2], a[0][3], b.x, b.y);
            mma16(d[1][nt], a[1][0], a[1][1], a[1][2], a[1][3], b.x, b.y);
        }
    }
}

// epilogue: D rows {g,g+8}, cols {f,f+1} -> bf16 row-major buf (stride S u32)
__device__ __forceinline__ void store_bf(u32* buf, int S, int g, int f, int mt,
                                         float4 v) {
    buf[(mt * 16 + g) * S + (f >> 1)]     = packbf(v.x, v.y);
    buf[(mt * 16 + g + 8) * S + (f >> 1)] = packbf(v.z, v.w);
}

// ---------------------------------------------------------------------------
__global__ void k_zero(int n_nodes) {
    int t0 = n_nodes * F_, t1 = t0 + n_nodes * C_ * 3, t2 = t1 + n_nodes, t3 = t2 + n_nodes;
    for (int i = blockIdx.x * blockDim.x + threadIdx.x; i < t3; i += gridDim.x * blockDim.x) {
        if (i < t0)       g_ef_sum[i] = 0.f;
        else if (i < t1)  g_x_acc[i - t0] = 0.f;
        else if (i < t2)  g_cnt_row[i - t1] = 0.f;
        else              g_cnt_col[i - t2] = 0.f;
    }
}

__global__ void k_prep(const float* __restrict__ x, const float* __restrict__ cw, int N) {
    int n = blockIdx.x * blockDim.x + threadIdx.x;
    if (n >= N) return;
    int s = 0; float px = 0.f, py = 0.f, pz = 0.f;
    #pragma unroll
    for (int i = 0; i < C_; ++i) {
        float w = cw[n * C_ + i];
        if (w != 0.f) {
            s++; px += x[n * 42 + i * 3]; py += x[n * 42 + i * 3 + 1]; pz += x[n * 42 + i * 3 + 2];
        }
    }
    g_csum[n] = s;
    float inv = 1.f / (float)(s > 0 ? s : 1);
    g_pooled[n * 3] = px * inv; g_pooled[n * 3 + 1] = py * inv; g_pooled[n * 3 + 2] = pz * inv;
}

// h -> bf16 image
__global__ void k_hprep(const float* __restrict__ h, int N) {
    int i = blockIdx.x * blockDim.x + threadIdx.x;
    if (i < N * 32) {
        float4 v = *(const float4*)(h + (size_t)i * 4);
        ((uint2*)g_hbf)[i] = make_uint2(packbf(v.x, v.y), packbf(v.z, v.w));
    }
}

// bf16 fragment images
__global__ void k_wprep(const float* __restrict__ e_w1, const float* __restrict__ e_w2,
                        const float* __restrict__ c_w1, const float* __restrict__ c_w2,
                        const float* __restrict__ rad_w, const float* __restrict__ n_w1,
                        const float* __restrict__ n_w2) {
    int t = blockIdx.x * blockDim.x + threadIdx.x;
    if (t >= 41472) return;
    int u = t, base; const float* W; int KST, Ncol;
    if      (u < 12288) { base = WB_E1; W = e_w1; KST = 24; Ncol = 128; }
    else if (u < 16384) { u -= 12288; base = WB_E2; W = e_w2;  KST = 8;  Ncol = 128; }
    else if (u < 20480) { u -= 16384; base = WB_C1; W = c_w1;  KST = 8;  Ncol = 128; }
    else if (u < 20992) { u -= 20480; base = WB_C2; W = c_w2;  KST = 8;  Ncol = 14;  }
    else if (u < 29184) { u -= 20992; base = WB_RW; W = rad_w; KST = 16; Ncol = 128; }
    else if (u < 37376) { u -= 29184; base = WB_N1; W = n_w1;  KST = 16; Ncol = 128; }
    else                { u -= 37376; base = WB_N2; W = n_w2;  KST = 8;  Ncol = 128; }
    int lane = u & 31, ks = (u >> 5) % KST, nt = u / (KST * 32);
    int g = lane >> 2, tig = lane & 3;
    int n = nt * 8 + g, k = ks * 16 + 2 * tig;
    uint2 e = make_uint2(0u, 0u);
    if (n < Ncol) {
        e.x = packbf(W[k * Ncol + n],       W[(k + 1) * Ncol + n]);
        e.y = packbf(W[(k + 8) * Ncol + n], W[(k + 9) * Ncol + n]);
    }
    ((uint2*)g_wt)[base + u] = e;
}

// ---------------------------------------------------------------------------
// K_FUSED — bf16 prologue mmas; 4 CTAs/SM target
// ---------------------------------------------------------------------------
#define SMEM_F (11136 * 4)

__global__ __launch_bounds__(256, 4) void k_fused(
    const float* __restrict__ x, const float* __restrict__ attr,
    const float* __restrict__ cw, const int* __restrict__ row,
    const int* __restrict__ col, const float* __restrict__ rad_b,
    const float* __restrict__ e_b1, const float* __restrict__ e_b2,
    const float* __restrict__ att_w, const float* __restrict__ att_b,
    const float* __restrict__ c_b1, const float* __restrict__ c_b2, int E)
{
    extern __shared__ u32 smu[];
    u32*   in_s   = smu;                    // [32][132] bf16 pairs
    u32*   bufA   = smu;                    // [32][68]
    float* cm_s   = (float*)(smu + 2176);   // 512
    float* gp     = (float*)(smu + 2688);   // 288
    float* gate_s = (float*)(smu + 2976);   // 32
    float* wscF   = (float*)(smu + 4224);   // 8 x 848 (phase 1)
    u32*   bufR   = smu + 4224;             // [32][68]
    u32*   bufT   = smu + 6400;             // [32][68]
    int*   s_row  = (int*)(smu + 11008);
    int*   s_col  = s_row + 32;
    int*   s_cs   = s_col + 32;
    float* inv_norm = (float*)(s_cs + 32);

    int tid = threadIdx.x, lane = tid & 31, w = tid >> 5;
    int g = lane >> 2, tig = lane & 3;
    int e0 = blockIdx.x * TIL;
    const uint2* gw = (const uint2*)g_wt;

    if (tid < TIL) {
        int e = e0 + tid; if (e >= E) e = E - 1;
        int r = row[e];
        s_row[tid] = r; s_col[tid] = col[e]; s_cs[tid] = g_csum[r];
    }
    __syncthreads();

    // ======== phase 1: radial einsum prologue (bf16 mma) ========
    {
        float* W = wscF + w * 848;
        float *s_T = W, *s_xr = W + 272, *s_xc = W + 320,
              *s_cwr = W + 368, *s_cwc = W + 384, *s_ar = W + 400, *s_ac = W + 624;

        float p_ar[7], p_ac[7];
        int p_r, p_c;
        {
            int e = e0 + w * 4; if (e >= E) e = E - 1;
            p_r = row[e]; p_c = col[e];
            #pragma unroll
            for (int q = 0; q < 7; ++q) {
                p_ar[q] = attr[p_r * 224 + q * 32 + lane];
                p_ac[q] = attr[p_c * 224 + q * 32 + lane];
            }
        }

        for (int it = 0; it < 4; ++it) {
            int m = w * 4 + it;
            int r = p_r, c = p_c;

            #pragma unroll
            for (int q = 0; q < 7; ++q) {
                s_ar[q * 32 + lane] = p_ar[q];
                s_ac[q * 32 + lane] = p_ac[q];
            }
            s_xr[lane] = x[r * 42 + lane];
            s_xc[lane] = x[c * 42 + lane];
            if (lane < 16) {
                s_xr[32 + lane] = (lane < 10) ? x[r * 42 + 32 + lane] : 0.f;
                s_xc[32 + lane] = (lane < 10) ? x[c * 42 + 32 + lane] : 0.f;
                s_cwr[lane] = (lane < 14) ? cw[r * C_ + lane] : 0.f;
                s_cwc[lane] = (lane < 14) ? cw[c * C_ + lane] : 0.f;
            }
            if (it < 3) {
                int e = e0 + m + 1; if (e >= E) e = E - 1;
                p_r = row[e]; p_c = col[e];
                #pragma unroll
                for (int q = 0; q < 7; ++q) {
                    p_ar[q] = attr[p_r * 224 + q * 32 + lane];
                    p_ac[q] = attr[p_c * 224 + q * 32 + lane];
                }
            }
            __syncwarp();

            // msg A-fragment values: rows {g, g+8}, cols {2tig,2tig+1,2tig+8,2tig+9}
            float msgv[2][4];
            {
                float xr0[3] = { s_xr[g * 3], s_xr[g * 3 + 1], s_xr[g * 3 + 2] };
                float xr1[3] = { s_xr[(g + 8) * 3], s_xr[(g + 8) * 3 + 1], s_xr[(g + 8) * 3 + 2] };
                float cw0 = s_cwr[g], cw1 = s_cwr[g + 8];
                #pragma unroll
                for (int jj = 0; jj < 4; ++jj) {
                    int cj = 2 * tig + (jj & 1) + (jj >> 1) * 8;
                    float xc0 = s_xc[cj * 3], xc1 = s_xc[cj * 3 + 1], xc2 = s_xc[cj * 3 + 2];
                    float cwc = s_cwc[cj];
                    float d0x = xr0[0] - xc0, d0y = xr0[1] - xc1, d0z = xr0[2] - xc2;
                    float d1x = xr1[0] - xc0, d1y = xr1[1] - xc1, d1z = xr1[2] - xc2;
                    msgv[0][jj] = sqrtf(d0x*d0x + d0y*d0y + d0z*d0z) * cw0 * cwc;
                    msgv[1][jj] = sqrtf(d1x*d1x + d1y*d1y + d1z*d1z) * cw1 * cwc;
                }
            }

            // T = msg @ ac  (one mma16 per n-tile)
            float4 dT[2] = {make_float4(0,0,0,0), make_float4(0,0,0,0)};
            {
                u32 a0 = packbf(msgv[0][0], msgv[0][1]);
                u32 a1 = packbf(msgv[1][0], msgv[1][1]);
                u32 a2 = packbf(msgv[0][2], msgv[0][3]);
                u32 a3 = packbf(msgv[1][2], msgv[1][3]);
                int kb0 = 2 * tig, kb1 = 2 * tig + 8;
                #pragma unroll
                for (int nt = 0; nt < 2; ++nt) {
                    int n = nt * 8 + g;
                    u32 b0 = packbf(s_ac[kb0 * 16 + n], s_ac[(kb0 + 1) * 16 + n]);
                    u32 b1 = (kb1 < 14)
                        ? packbf(s_ac[kb1 * 16 + n],
                                 (kb1 + 1 < 14) ? s_ac[(kb1 + 1) * 16 + n] : 0.f)
                        : 0u;
                    mma16(dT[nt], a0, a1, a2, a3, b0, b1);
                }
            }
            #pragma unroll
            for (int nt = 0; nt < 2; ++nt) {
                int fc = nt * 8 + 2 * tig;
                s_T[g * 17 + fc]           = dT[nt].x;
                s_T[g * 17 + fc + 1]       = dT[nt].y;
                s_T[(g + 8) * 17 + fc]     = dT[nt].z;
                s_T[(g + 8) * 17 + fc + 1] = dT[nt].w;
            }
            __syncwarp();

            // R = ar^T @ T  (one mma16 per n-tile); T rows >=14 are zero
            float4 dR[2] = {make_float4(0,0,0,0), make_float4(0,0,0,0)};
            {
                int kb0 = 2 * tig, kb1 = 2 * tig + 8;
                u32 a0 = packbf(s_ar[kb0 * 16 + g],     s_ar[(kb0 + 1) * 16 + g]);
                u32 a1 = packbf(s_ar[kb0 * 16 + g + 8], s_ar[(kb0 + 1) * 16 + g + 8]);
                u32 a2 = 0u, a3 = 0u;
                if (kb1 < 14) {
                    float v2 = (kb1 + 1 < 14) ? s_ar[(kb1 + 1) * 16 + g] : 0.f;
                    float v3 = (kb1 + 1 < 14) ? s_ar[(kb1 + 1) * 16 + g + 8] : 0.f;
                    a2 = packbf(s_ar[kb1 * 16 + g], v2);
                    a3 = packbf(s_ar[kb1 * 16 + g + 8], v3);
                }
                #pragma unroll
                for (int nt = 0; nt < 2; ++nt) {
                    int n = nt * 8 + g;
                    u32 b0 = packbf(s_T[kb0 * 17 + n], s_T[(kb0 + 1) * 17 + n]);
                    u32 b1 = packbf(s_T[kb1 * 17 + n], s_T[(kb1 + 1) * 17 + n]);
                    mma16(dR[nt], a0, a1, a2, a3, b0, b1);
                }
            }

            float ss = dR[0].x*dR[0].x + dR[0].y*dR[0].y + dR[0].z*dR[0].z + dR[0].w*dR[0].w
                     + dR[1].x*dR[1].x + dR[1].y*dR[1].y + dR[1].z*dR[1].z + dR[1].w*dR[1].w;
            #pragma unroll
            for (int o = 16; o; o >>= 1) ss += __shfl_xor_sync(0xffffffffu, ss, o);
            if (lane == 0) inv_norm[m] = 1.f / (sqrtf(ss) + 1.f);

            #pragma unroll
            for (int nt = 0; nt < 2; ++nt) {
                int fc = nt * 8 + 2 * tig;
                in_s[m * 132 + ((g * 16 + fc) >> 1)]       = packbf(dR[nt].x, dR[nt].y);
                in_s[m * 132 + (((g + 8) * 16 + fc) >> 1)] = packbf(dR[nt].z, dR[nt].w);
            }
            __syncwarp();
        }
    }
    __syncthreads();

    // ======== phase 2: radial GEMM K=256 (bf16) ========
    float4 d[2][2];
    d[0][0] = d[0][1] = d[1][0] = d[1][1] = make_float4(0.f, 0.f, 0.f, 0.f);
    gemm_bf<132, 2>(in_s, gw + WB_RW, w * 2, 0, 16, 16, g, tig, lane, d);

    // epilogue before the barrier (bufR aliases dead wscF)
    #pragma unroll
    for (int mt = 0; mt < 2; ++mt)
        #pragma unroll
        for (int nt = 0; nt < 2; ++nt) {
            int f = w * 16 + nt * 8 + 2 * tig;
            float2 rb = *(const float2*)(rad_b + f);
            int e = mt * 16 + g;
            float na = inv_norm[e], nb = inv_norm[e + 8];
            bufR[(mt * 16 + g) * 68 + (f >> 1)] =
                packbf((d[mt][nt].x + rb.x) * na, (d[mt][nt].y + rb.y) * na);
            bufR[(mt * 16 + g + 8) * 68 + (f >> 1)] =
                packbf((d[mt][nt].z + rb.x) * nb, (d[mt][nt].w + rb.y) * nb);
        }
    __syncthreads();

    // stage h[row] -> bufA (raw bf16 copy)
    for (int i = tid; i < 1024; i += 256) {
        int e = i >> 5, q = i & 31;
        *(uint2*)(bufA + e * 68 + q * 2) =
            *(const uint2*)(g_hbf + (size_t)s_row[e] * 64 + q * 2);
    }
    __syncthreads();

    // ======== GEMM1 (K=384) ========
    d[0][0] = d[0][1] = d[1][0] = d[1][1] = make_float4(0.f, 0.f, 0.f, 0.f);
    gemm_bf<68, 2>(bufA, gw + WB_E1, w * 2, 0, 8, 24, g, tig, lane, d);
    __syncthreads();
    for (int i = tid; i < 1024; i += 256) {       // stage h[col] -> bufA
        int e = i >> 5, q = i & 31;
        *(uint2*)(bufA + e * 68 + q * 2) =
            *(const uint2*)(g_hbf + (size_t)s_col[e] * 64 + q * 2);
    }
    __syncthreads();
    gemm_bf<68, 2>(bufA, gw + WB_E1, w * 2, 8, 8, 24, g, tig, lane, d);
    gemm_bf<68, 2>(bufR, gw + WB_E1, w * 2, 16, 8, 24, g, tig, lane, d);

    // ep1: t1 = silu(D + e_b1) -> bufT
    #pragma unroll
    for (int mt = 0; mt < 2; ++mt)
        #pragma unroll
        for (int nt = 0; nt < 2; ++nt) {
            int f = w * 16 + nt * 8 + 2 * tig;
            float2 bb = *(const float2*)(e_b1 + f);
            store_bf(bufT, 68, g, f, mt,
                make_float4(silu_(d[mt][nt].x + bb.x), silu_(d[mt][nt].y + bb.y),
                            silu_(d[mt][nt].z + bb.x), silu_(d[mt][nt].w + bb.y)));
        }
    __syncthreads();

    // ======== GEMM2: e_w2 ========
    d[0][0] = d[0][1] = d[1][0] = d[1][1] = make_float4(0.f, 0.f, 0.f, 0.f);
    gemm_bf<68, 2>(bufT, gw + WB_E2, w * 2, 0, 8, 8, g, tig, lane, d);

    // ep2: t2 = silu(+e_b2); gate; ef -> bufR + vector reds
    {
        float p[4] = {0.f, 0.f, 0.f, 0.f};
        #pragma unroll
        for (int mt = 0; mt < 2; ++mt)
            #pragma unroll
            for (int nt = 0; nt < 2; ++nt) {
                int f = w * 16 + nt * 8 + 2 * tig;
                float2 bb = *(const float2*)(e_b2 + f);
                float2 aw = *(const float2*)(att_w + f);
                float c0 = silu_(d[mt][nt].x + bb.x), c1 = silu_(d[mt][nt].y + bb.y);
                float c2 = silu_(d[mt][nt].z + bb.x), c3 = silu_(d[mt][nt].w + bb.y);
                d[mt][nt] = make_float4(c0, c1, c2, c3);
                p[mt * 2 + 0] += c0 * aw.x + c1 * aw.y;
                p[mt * 2 + 1] += c2 * aw.x + c3 * aw.y;
            }
        #pragma unroll
        for (int o = 1; o <= 2; o <<= 1)
            #pragma unroll
            for (int q = 0; q < 4; ++q) p[q] += __shfl_xor_sync(0xffffffffu, p[q], o);
        if (tig == 0) {
            gp[w * 36 + g]      = p[0];
            gp[w * 36 + g + 8]  = p[1];
            gp[w * 36 + g + 16] = p[2];
            gp[w * 36 + g + 24] = p[3];
        }
    }
    __syncthreads();
    if (tid < TIL) {
        float s = __ldg(att_b);
        #pragma unroll
        for (int j = 0; j < 8; ++j) s += gp[j * 36 + tid];
        gate_s[tid] = sigm_(s);
    }
    __syncthreads();
    #pragma unroll
    for (int mt = 0; mt < 2; ++mt) {
        int ea = mt * 16 + g, eb = ea + 8;
        float ga = gate_s[ea], gb = gate_s[eb];
        #pragma unroll
        for (int nt = 0; nt < 2; ++nt) {
            int f = w * 16 + nt * 8 + 2 * tig;
            float c0 = d[mt][nt].x * ga, c1 = d[mt][nt].y * ga;
            float c2 = d[mt][nt].z * gb, c3 = d[mt][nt].w * gb;
            store_bf(bufR, 68, g, f, mt, make_float4(c0, c1, c2, c3));
            if (e0 + ea < E)
                red2(g_ef_sum + (size_t)s_col[ea] * F_ + f, c0, c1);
            if (e0 + eb < E)
                red2(g_ef_sum + (size_t)s_col[eb] * F_ + f, c2, c3);
        }
    }
    if (tid < TIL && e0 + tid < E) {
        atomicAdd(&g_cnt_col[s_col[tid]], 1.f);
        atomicAdd(&g_cnt_row[s_row[tid]], 1.f);
    }
    __syncthreads();

    // ======== GEMM3: c_w1 ========
    d[0][0] = d[0][1] = d[1][0] = d[1][1] = make_float4(0.f, 0.f, 0.f, 0.f);
    gemm_bf<68, 2>(bufR, gw + WB_C1, w * 2, 0, 8, 8, g, tig, lane, d);
    #pragma unroll
    for (int mt = 0; mt < 2; ++mt)
        #pragma unroll
        for (int nt = 0; nt < 2; ++nt) {
            int f = w * 16 + nt * 8 + 2 * tig;
            float2 bb = *(const float2*)(c_b1 + f);
            store_bf(bufT, 68, g, f, mt,
                make_float4(silu_(d[mt][nt].x + bb.x), silu_(d[mt][nt].y + bb.y),
                            silu_(d[mt][nt].z + bb.x), silu_(d[mt][nt].w + bb.y)));
        }
    __syncthreads();

    // ======== GEMM4: c_w2 (N=16, warps 0-1) ========
    if (w < 2) {
        float4 dc[2] = {make_float4(0,0,0,0), make_float4(0,0,0,0)};
        #pragma unroll
        for (int ks = 0; ks < 8; ++ks) {
            uint2 b = gw[WB_C2 + ((size_t)w * 8 + ks) * 32 + lane];
            #pragma unroll
            for (int mt = 0; mt < 2; ++mt) {
                const u32* r0 = bufT + (mt * 16 + g) * 68 + ks * 8;
                const u32* r1 = bufT + (mt * 16 + g + 8) * 68 + ks * 8;
                mma16(dc[mt], r0[tig], r1[tig], r0[tig + 4], r1[tig + 4], b.x, b.y);
            }
        }
        int o = w * 8 + 2 * tig;
        float cbx = (o < 14)     ? __ldg(c_b2 + o)     : 0.f;
        float cby = (o + 1 < 14) ? __ldg(c_b2 + o + 1) : 0.f;
        #pragma unroll
        for (int mt = 0; mt < 2; ++mt) {
            *(float2*)(cm_s + (mt * 16 + g) * 16 + o) =
                make_float2(dc[mt].x + cbx, dc[mt].y + cby);
            *(float2*)(cm_s + (mt * 16 + g + 8) * 16 + o) =
                make_float2(dc[mt].z + cbx, dc[mt].w + cby);
        }
    }
    __syncthreads();

    // ======== roller pooling + x scatter ========
    for (int idx = tid; idx < TIL * 42; idx += 256) {
        int m = idx / 42, rem = idx - m * 42;
        int e = e0 + m;
        if (e < E) {
            int i = rem / 3, dd = rem - i * 3;
            int ws = 15 - s_cs[m];
            if (ws < 1)  ws = 1;
            if (ws > 14) ws = 14;
            int end = i + ws; if (end > 14) end = 14;
            float ps = 0.f;
            for (int q = i; q < end; ++q) ps += cm_s[m * 16 + q];
            float pooled = ps / (float)ws;
            float cd = x[(size_t)s_row[m] * 42 + rem] - g_pooled[s_col[m] * 3 + dd];
            atomicAdd(&g_x_acc[(size_t)s_row[m] * 42 + rem], cd * pooled);
        }
    }
}

// ---------------------------------------------------------------------------
// K_NODE
// ---------------------------------------------------------------------------
#define SMEM_N (7008 * 4)
__global__ __launch_bounds__(128) void k_node(
    const float* __restrict__ h, const float* __restrict__ x,
    const float* __restrict__ n_b1, const float* __restrict__ n_b2,
    const float* __restrict__ ln_g, const float* __restrict__ ln_b,
    float* __restrict__ out, int N)
{
    extern __shared__ u32 smu[];
    u32*   in_s = smu;
    u32*   bufT = smu + 4224;
    float* gp1  = (float*)(smu + 6400);
    float* gp2  = gp1 + 144;
    float* mu_s = gp2 + 144;
    float* rs_s = mu_s + 32;
    float* ic_s = rs_s + 32;

    int tid = threadIdx.x, lane = tid & 31, w = tid >> 5;
    int g = lane >> 2, tig = lane & 3, nt0 = w * 4;
    int n0 = blockIdx.x * TIL;
    const uint2* gw = (const uint2*)g_wt;

    if (tid < TIL) {
        int n = n0 + tid;
        float c = (n < N) ? g_cnt_col[n] : 1.f;
        ic_s[tid] = 1.f / fmaxf(c, 1.f);
    }
    __syncthreads();

    for (int i = tid; i < 2048; i += 128) {
        int e = i >> 6, q = i & 63;
        int n = n0 + e; if (n >= N) n = N - 1;
        if (q < 32) {
            *(uint2*)(in_s + e * 132 + q * 2) =
                *(const uint2*)(g_hbf + (size_t)n * 64 + q * 2);
        } else {
            float4 v = *(const float4*)(g_ef_sum + (size_t)n * F_ + (q - 32) * 4);
            float ic = ic_s[e];
            *(uint2*)(in_s + e * 132 + q * 2) =
                make_uint2(packbf(v.x * ic, v.y * ic), packbf(v.z * ic, v.w * ic));
        }
    }
    __syncthreads();

    float4 d[2][4];
    #pragma unroll
    for (int mt = 0; mt < 2; ++mt)
        #pragma unroll
        for (int nt = 0; nt < 4; ++nt) d[mt][nt] = make_float4(0.f, 0.f, 0.f, 0.f);
    gemm_bf<132, 4>(in_s, gw + WB_N1, nt0, 0, 16, 16, g, tig, lane, d);
    #pragma unroll
    for (int mt = 0; mt < 2; ++mt)
        #pragma unroll
        for (int nt = 0; nt < 4; ++nt) {
            int f = w * 32 + nt * 8 + 2 * tig;
            float2 bb = *(const float2*)(n_b1 + f);
            store_bf(bufT, 68, g, f, mt,
                make_float4(silu_(d[mt][nt].x + bb.x), silu_(d[mt][nt].y + bb.y),
                            silu_(d[mt][nt].z + bb.x), silu_(d[mt][nt].w + bb.y)));
        }
    __syncthreads();

    #pragma unroll
    for (int mt = 0; mt < 2; ++mt)
        #pragma unroll
        for (int nt = 0; nt < 4; ++nt) d[mt][nt] = make_float4(0.f, 0.f, 0.f, 0.f);
    gemm_bf<68, 4>(bufT, gw + WB_N2, nt0, 0, 8, 8, g, tig, lane, d);

    {
        float p1[4] = {0,0,0,0}, p2[4] = {0,0,0,0};
        #pragma unroll
        for (int mt = 0; mt < 2; ++mt) {
            int na = n0 + mt * 16 + g, nb = na + 8;
            if (na >= N) na = N - 1;
            if (nb >= N) nb = N - 1;
            #pragma unroll
            for (int nt = 0; nt < 4; ++nt) {
                int f = w * 32 + nt * 8 + 2 * tig;
                float2 bb = *(const float2*)(n_b2 + f);
                float2 ra = *(const float2*)(h + (size_t)na * F_ + f);
                float2 rb = *(const float2*)(h + (size_t)nb * F_ + f);
                float h0 = ra.x + d[mt][nt].x + bb.x, h1 = ra.y + d[mt][nt].y + bb.y;
                float h2 = rb.x + d[mt][nt].z + bb.x, h3 = rb.y + d[mt][nt].w + bb.y;
                d[mt][nt] = make_float4(h0, h1, h2, h3);
                p1[mt*2]   += h0 + h1;  p2[mt*2]   += h0*h0 + h1*h1;
                p1[mt*2+1] += h2 + h3;  p2[mt*2+1] += h2*h2 + h3*h3;
            }
        }
        #pragma unroll
        for (int o = 1; o <= 2; o <<= 1)
            #pragma unroll
            for (int q = 0; q < 4; ++q) {
                p1[q] += __shfl_xor_sync(0xffffffffu, p1[q], o);
                p2[q] += __shfl_xor_sync(0xffffffffu, p2[q], o);
            }
        if (tig == 0) {
            #pragma unroll
            for (int q = 0; q < 4; ++q) {
                int e = (q >> 1) * 16 + g + (q & 1) * 8;
                gp1[w * 36 + e] = p1[q];
                gp2[w * 36 + e] = p2[q];
            }
        }
    }
    __syncthreads();
    if (tid < TIL) {
        float s1 = gp1[tid] + gp1[36 + tid] + gp1[72 + tid] + gp1[108 + tid];
        float s2 = gp2[tid] + gp2[36 + tid] + gp2[72 + tid] + gp2[108 + tid];
        float mu = s1 * (1.f / 128.f);
        float var = fmaxf(s2 * (1.f / 128.f) - mu * mu, 0.f);
        mu_s[tid] = mu;
        rs_s[tid] = rsqrtf(var + 1e-5f);
    }
    __syncthreads();

    #pragma unroll
    for (int mt = 0; mt < 2; ++mt) {
        int ea = mt * 16 + g, eb = ea + 8;
        int na = n0 + ea, nb = n0 + eb;
        float mua = mu_s[ea], rsa = rs_s[ea];
        float mub = mu_s[eb], rsb = rs_s[eb];
        #pragma unroll
        for (int nt = 0; nt < 4; ++nt) {
            int f = w * 32 + nt * 8 + 2 * tig;
            float2 gv = *(const float2*)(ln_g + f);
            float2 bv = *(const float2*)(ln_b + f);
            if (na < N)
                *(float2*)(out + (size_t)na * F_ + f) = make_float2(
                    (d[mt][nt].x - mua) * rsa * gv.x + bv.x,
                    (d[mt][nt].y - mua) * rsa * gv.y + bv.y);
            if (nb < N)
                *(float2*)(out + (size_t)nb * F_ + f) = make_float2(
                    (d[mt][nt].z - mub) * rsb * gv.x + bv.x,
                    (d[mt][nt].w - mub) * rsb * gv.y + bv.y);
        }
    }

    float* out_x = out + (size_t)N * F_;
    for (int idx = tid; idx < TIL * 42; idx += 128) {
        int m = idx / 42, rem = idx - m * 42;
        int n = n0 + m;
        if (n < N)
            out_x[(size_t)n * 42 + rem] = x[(size_t)n * 42 + rem] +
                g_x_acc[(size_t)n * 42 + rem] / fmaxf(g_cnt_row[n], 1.f);
    }
}

// ---------------------------------------------------------------------------
extern "C" void kernel_launch(void* const* d_in, const int* in_sizes, int n_in,
                              void* d_out, int out_size) {
    const float* h     = (const float*)d_in[0];
    const float* x     = (const float*)d_in[1];
    const float* attr  = (const float*)d_in[2];
    const float* cw    = (const float*)d_in[3];
    const int*   row   = (const int*)d_in[4];
    const int*   col   = (const int*)d_in[5];
    const float* rad_w = (const float*)d_in[6];
    const float* rad_b = (const float*)d_in[7];
    const float* e_w1  = (const float*)d_in[8];
    const float* e_b1  = (const float*)d_in[9];
    const float* e_w2  = (const float*)d_in[10];
    const float* e_b2  = (const float*)d_in[11];
    const float* att_w = (const float*)d_in[12];
    const float* att_b = (const float*)d_in[13];
    const float* c_w1  = (const float*)d_in[14];
    const float* c_b1  = (const float*)d_in[15];
    const float* c_w2  = (const float*)d_in[16];
    const float* c_b2  = (const float*)d_in[17];
    const float* n_w1  = (const float*)d_in[18];
    const float* n_b1  = (const float*)d_in[19];
    const float* n_w2  = (const float*)d_in[20];
    const float* n_b2  = (const float*)d_in[21];
    const float* ln_g  = (const float*)d_in[22];
    const float* ln_b  = (const float*)d_in[23];

    int N = in_sizes[0] / F_;
    int E = in_sizes[4];

    cudaFuncSetAttribute(k_fused, cudaFuncAttributeMaxDynamicSharedMemorySize, SMEM_F);
    cudaFuncSetAttribute(k_node,  cudaFuncAttributeMaxDynamicSharedMemorySize, SMEM_N);

    k_zero<<<256, 256>>>(N);
    k_prep<<<(N + 255) / 256, 256>>>(x, cw, N);
    k_hprep<<<(N * 32 + 255) / 256, 256>>>(h, N);
    k_wprep<<<162, 256>>>(e_w1, e_w2, c_w1, c_w2, rad_w, n_w1, n_w2);
    k_fused<<<(E + TIL - 1) / TIL, 256, SMEM_F>>>(x, attr, cw, row, col, rad_b,
                                                  e_b1, e_b2, att_w, att_b,
                                                  c_b1, c_b2, E);
    k_node<<<(N + TIL - 1) / TIL, 128, SMEM_N>>>(h, x, n_b1, n_b2,
                                                 ln_g, ln_b, (float*)d_out, N);
}